// round 1
// baseline (speedup 1.0000x reference)
#include <cuda_runtime.h>
#include <math.h>

#define B 8
#define N 2048
#define C 128
#define F 128
#define GALPHA 0.2f

#define TI 64
#define TJ 32

__device__ float g_h[B*N*F];
__device__ float g_e1[B*N];
__device__ float g_e2[B*N];
__device__ float g_P1[B*N];
__device__ float g_N1[B*N];
__device__ float g_P2[B*N];
__device__ float g_N2[B*N];

// Kernel 1: h = text @ W.  Block = 32 rows x 128 cols, 128 threads.
__global__ __launch_bounds__(128) void k_gemm_h(const float* __restrict__ text,
                                                const float* __restrict__ W) {
    __shared__ float a_sh[32 * C];
    int t = threadIdx.x;
    int row0 = blockIdx.x * 32;

    const float4* src = (const float4*)(text + (size_t)row0 * C);
    float4* dst = (float4*)a_sh;
#pragma unroll
    for (int i = 0; i < 8; ++i) dst[t + i * 128] = src[t + i * 128];
    __syncthreads();

    float acc[32];
#pragma unroll
    for (int r = 0; r < 32; ++r) acc[r] = 0.f;

#pragma unroll 4
    for (int c = 0; c < C; ++c) {
        float w = W[c * F + t];
#pragma unroll
        for (int r = 0; r < 32; ++r) acc[r] = fmaf(a_sh[r * C + c], w, acc[r]);
    }
#pragma unroll
    for (int r = 0; r < 32; ++r) g_h[(size_t)(row0 + r) * F + t] = acc[r];
}

// Kernel 2: e1/e2 per node + factored exp tables. One warp per row.
__global__ __launch_bounds__(256) void k_e(const float* __restrict__ a) {
    int warp = threadIdx.x >> 5, lane = threadIdx.x & 31;
    int row = blockIdx.x * 8 + warp;
    const float* hrow = g_h + (size_t)row * F;
    float s1 = 0.f, s2 = 0.f;
#pragma unroll
    for (int i = 0; i < 4; ++i) {
        int f = lane + i * 32;
        float hv = hrow[f];
        s1 = fmaf(hv, a[f], s1);
        s2 = fmaf(hv, a[F + f], s2);
    }
#pragma unroll
    for (int o = 16; o > 0; o >>= 1) {
        s1 += __shfl_xor_sync(0xffffffffu, s1, o);
        s2 += __shfl_xor_sync(0xffffffffu, s2, o);
    }
    if (lane == 0) {
        g_e1[row] = s1; g_e2[row] = s2;
        g_P1[row] = expf(s1); g_N1[row] = expf(GALPHA * s1);
        g_P2[row] = expf(s2); g_N2[row] = expf(GALPHA * s2);
    }
}

// Kernel 3: fused softmax-weights + attention@h GEMM + elu epilogue.
// Block tile: TI=64 rows x F=128 cols; 256 threads, thread tile 4x8.
__global__ __launch_bounds__(256, 2) void k_attn(float* __restrict__ out) {
    __shared__ float h_sh[TJ][F];
    __shared__ float w_sh[TI][TJ + 1];   // +1 pad: kill 2-way conflict on reads
    __shared__ float e1_sh[TI], P1_sh[TI], N1_sh[TI], den_sh[TI];

    int t = threadIdx.x;
    int b = blockIdx.y;
    int i0 = blockIdx.x * TI;
    int base = b * N;

    if (t < TI) {
        e1_sh[t] = g_e1[base + i0 + t];
        P1_sh[t] = g_P1[base + i0 + t];
        N1_sh[t] = g_N1[base + i0 + t];
    }

    int tx = t & 15, ty = t >> 4;        // FMA mapping: rows ty*4+r, cols tx*8+k
    int wrow0 = t >> 5;                  // weight-gen mapping: rows wrow0+k*8
    int wlane = t & 31;                  // jj within tile

    float acc[4][8];
#pragma unroll
    for (int r = 0; r < 4; ++r)
#pragma unroll
        for (int k = 0; k < 8; ++k) acc[r][k] = 0.f;
    float den[8];
#pragma unroll
    for (int k = 0; k < 8; ++k) den[k] = 0.f;

    __syncthreads();

    for (int j0 = 0; j0 < N; j0 += TJ) {
        // stage h tile (32x128 floats, coalesced float4)
        const float4* hsrc = (const float4*)(g_h + (size_t)(base + j0) * F);
        float4* hdst = (float4*)&h_sh[0][0];
#pragma unroll
        for (int i = 0; i < 4; ++i) hdst[t + i * 256] = hsrc[t + i * 256];

        // on-the-fly softmax numerators: w_ij = (e1+e2>0) ? P1*P2 : N1*N2
        float e2v = g_e2[base + j0 + wlane];
        float P2v = g_P2[base + j0 + wlane];
        float N2v = g_N2[base + j0 + wlane];
#pragma unroll
        for (int k = 0; k < 8; ++k) {
            int row = wrow0 + k * 8;
            float s = e1_sh[row] + e2v;
            float w = (s > 0.f) ? (P1_sh[row] * P2v) : (N1_sh[row] * N2v);
            w_sh[row][wlane] = w;
            den[k] += w;
        }
        __syncthreads();

        // GEMM micro-tile: 32 FMA per 6 LDS
#pragma unroll 8
        for (int jj = 0; jj < TJ; ++jj) {
            float4 h0 = *(const float4*)&h_sh[jj][tx * 8];
            float4 h1 = *(const float4*)&h_sh[jj][tx * 8 + 4];
#pragma unroll
            for (int r = 0; r < 4; ++r) {
                float w = w_sh[ty * 4 + r][jj];
                acc[r][0] = fmaf(w, h0.x, acc[r][0]);
                acc[r][1] = fmaf(w, h0.y, acc[r][1]);
                acc[r][2] = fmaf(w, h0.z, acc[r][2]);
                acc[r][3] = fmaf(w, h0.w, acc[r][3]);
                acc[r][4] = fmaf(w, h1.x, acc[r][4]);
                acc[r][5] = fmaf(w, h1.y, acc[r][5]);
                acc[r][6] = fmaf(w, h1.z, acc[r][6]);
                acc[r][7] = fmaf(w, h1.w, acc[r][7]);
            }
        }
        __syncthreads();
    }

    // reduce per-row softmax denominators (reuse w_sh as scratch)
#pragma unroll
    for (int k = 0; k < 8; ++k) w_sh[wrow0 + k * 8][wlane] = den[k];
    __syncthreads();
    if (t < TI) {
        float s = 0.f;
#pragma unroll
        for (int jj = 0; jj < TJ; ++jj) s += w_sh[t][jj];
        den_sh[t] = s;
    }
    __syncthreads();

    // epilogue: out = elu(h_prime + 0.2*h)
#pragma unroll
    for (int r = 0; r < 4; ++r) {
        int row = ty * 4 + r;
        size_t gi = (size_t)(base + i0 + row) * F + tx * 8;
        float dinv = 1.f / den_sh[row];
        float4 h0 = *(const float4*)(g_h + gi);
        float4 h1 = *(const float4*)(g_h + gi + 4);
        float hv[8] = {h0.x, h0.y, h0.z, h0.w, h1.x, h1.y, h1.z, h1.w};
        float o[8];
#pragma unroll
        for (int k = 0; k < 8; ++k) {
            float x = fmaf(acc[r][k], dinv, GALPHA * hv[k]);
            o[k] = (x > 0.f) ? x : expm1f(x);
        }
        float4 o0 = {o[0], o[1], o[2], o[3]};
        float4 o1 = {o[4], o[5], o[6], o[7]};
        *(float4*)(out + gi) = o0;
        *(float4*)(out + gi + 4) = o1;
    }
}

extern "C" void kernel_launch(void* const* d_in, const int* in_sizes, int n_in,
                              void* d_out, int out_size) {
    const float* text = (const float*)d_in[0];
    // d_in[1] = adj : unused by the reference computation
    const float* W = (const float*)d_in[2];
    const float* a = (const float*)d_in[3];
    float* out = (float*)d_out;

    k_gemm_h<<<(B * N) / 32, 128>>>(text, W);
    k_e<<<(B * N) / 8, 256>>>(a);
    dim3 g2(N / TI, B);
    k_attn<<<g2, 256>>>(out);
}

// round 2
// speedup vs baseline: 4.8946x; 4.8946x over previous
#include <cuda_runtime.h>
#include <math.h>

#define B 8
#define N 2048
#define C 128
#define F 128
#define GALPHA 0.2f
#define NCHUNK 8
#define CHUNK 256   /* N / NCHUNK */

__device__ float g_h[B*N*F];
__device__ float g_e1[B*N], g_e2[B*N];
__device__ float g_P1[B*N], g_N1[B*N];
__device__ float g_P2[B*N], g_N2[B*N];
__device__ float g_negs[B*N];          // -e2, sorted ascending (== e2 descending)
__device__ int   g_perm[B*N];          // original index per sorted slot
__device__ float g_SP[B*N*F];          // chunk-local exclusive prefix of P2*h (sorted order)
__device__ float g_SN[B*N*F];
__device__ float g_offP[B*(NCHUNK+1)*F];  // per-chunk exclusive offsets (+ total at [8])
__device__ float g_offN[B*(NCHUNK+1)*F];
__device__ float g_sP[B*(N+1)];        // scalar exclusive prefixes of P2 / N2
__device__ float g_sN[B*(N+1)];

// ---------------------------------------------------------------------------
// Kernel 1: h = text @ W  (64x128 block tile, 256 thr, 4x8 thread tile)
//           + fused per-row e1/e2 + exp tables epilogue
// ---------------------------------------------------------------------------
__global__ __launch_bounds__(256) void k_gemm_h(const float* __restrict__ text,
                                                const float* __restrict__ W,
                                                const float* __restrict__ a) {
    __shared__ float a_sh[64][33];
    __shared__ float W_sh[32][128];
    __shared__ float avec[2 * F];

    int t = threadIdx.x;
    int row0 = blockIdx.x * 64;
    if (t < 64) ((float4*)avec)[t] = ((const float4*)a)[t];

    int tx = t & 15, ty = t >> 4;

    float acc[4][8];
#pragma unroll
    for (int r = 0; r < 4; ++r)
#pragma unroll
        for (int k = 0; k < 8; ++k) acc[r][k] = 0.f;

    for (int k0 = 0; k0 < C; k0 += 32) {
        // text tile 64x32 (scalar STS: provably conflict-free with 33-pad)
#pragma unroll
        for (int i = 0; i < 2; ++i) {
            int idx = t + i * 256;
            int r = idx >> 3, c4 = idx & 7;
            float4 v = *(const float4*)(text + (size_t)(row0 + r) * C + k0 + c4 * 4);
            a_sh[r][c4 * 4 + 0] = v.x;
            a_sh[r][c4 * 4 + 1] = v.y;
            a_sh[r][c4 * 4 + 2] = v.z;
            a_sh[r][c4 * 4 + 3] = v.w;
        }
        // W tile 32x128
#pragma unroll
        for (int i = 0; i < 4; ++i) {
            int idx = t + i * 256;
            int kr = idx >> 5, f4 = idx & 31;
            *(float4*)&W_sh[kr][f4 * 4] =
                *(const float4*)(W + (size_t)(k0 + kr) * F + f4 * 4);
        }
        __syncthreads();

#pragma unroll
        for (int jj = 0; jj < 32; ++jj) {
            float4 w0 = *(const float4*)&W_sh[jj][tx * 8];
            float4 w1 = *(const float4*)&W_sh[jj][tx * 8 + 4];
#pragma unroll
            for (int r = 0; r < 4; ++r) {
                float av = a_sh[ty * 4 + r][jj];
                acc[r][0] = fmaf(av, w0.x, acc[r][0]);
                acc[r][1] = fmaf(av, w0.y, acc[r][1]);
                acc[r][2] = fmaf(av, w0.z, acc[r][2]);
                acc[r][3] = fmaf(av, w0.w, acc[r][3]);
                acc[r][4] = fmaf(av, w1.x, acc[r][4]);
                acc[r][5] = fmaf(av, w1.y, acc[r][5]);
                acc[r][6] = fmaf(av, w1.z, acc[r][6]);
                acc[r][7] = fmaf(av, w1.w, acc[r][7]);
            }
        }
        __syncthreads();
    }

    // epilogue: store h, compute e1/e2 per row (reduce over tx = 16 lanes)
#pragma unroll
    for (int r = 0; r < 4; ++r) {
        int row = row0 + ty * 4 + r;
        size_t gi = (size_t)row * F + tx * 8;
        float4 o0 = {acc[r][0], acc[r][1], acc[r][2], acc[r][3]};
        float4 o1 = {acc[r][4], acc[r][5], acc[r][6], acc[r][7]};
        *(float4*)(g_h + gi) = o0;
        *(float4*)(g_h + gi + 4) = o1;

        float p1 = 0.f, p2 = 0.f;
#pragma unroll
        for (int k = 0; k < 8; ++k) {
            p1 = fmaf(acc[r][k], avec[tx * 8 + k], p1);
            p2 = fmaf(acc[r][k], avec[F + tx * 8 + k], p2);
        }
#pragma unroll
        for (int o = 8; o > 0; o >>= 1) {
            p1 += __shfl_xor_sync(0xffffffffu, p1, o);
            p2 += __shfl_xor_sync(0xffffffffu, p2, o);
        }
        if (tx == 0) {
            g_e1[row] = p1;
            g_e2[row] = p2;
            g_P1[row] = expf(p1);
            g_N1[row] = expf(GALPHA * p1);
            g_P2[row] = expf(p2);
            g_N2[row] = expf(GALPHA * p2);
        }
    }
}

// ---------------------------------------------------------------------------
// Kernel 2: per-batch bitonic sort of (-e2) ascending, with index payload
// ---------------------------------------------------------------------------
__global__ __launch_bounds__(1024) void k_sort() {
    __shared__ float key[N];
    __shared__ int   sid[N];
    int b = blockIdx.x, t = threadIdx.x;

    for (int j = t; j < N; j += 1024) { key[j] = -g_e2[b * N + j]; sid[j] = j; }
    __syncthreads();

    for (int k2 = 2; k2 <= N; k2 <<= 1) {
        for (int j2 = k2 >> 1; j2 > 0; j2 >>= 1) {
            for (int tt = t; tt < N; tt += 1024) {
                int ixj = tt ^ j2;
                if (ixj > tt) {
                    bool up = ((tt & k2) == 0);
                    float ka = key[tt], kb = key[ixj];
                    if ((ka > kb) == up) {
                        key[tt] = kb; key[ixj] = ka;
                        int tmp = sid[tt]; sid[tt] = sid[ixj]; sid[ixj] = tmp;
                    }
                }
            }
            __syncthreads();
        }
    }
    for (int j = t; j < N; j += 1024) {
        g_negs[b * N + j] = key[j];
        g_perm[b * N + j] = sid[j];
    }
}

// ---------------------------------------------------------------------------
// Kernel 3: scalar exclusive prefixes of P2/N2 in sorted order (Hillis-Steele)
// ---------------------------------------------------------------------------
__global__ __launch_bounds__(1024) void k_scan_scalar() {
    __shared__ float sp[1024], sn[1024];
    int b = blockIdx.x, t = threadIdx.x;
    int p0 = g_perm[b * N + 2 * t], p1 = g_perm[b * N + 2 * t + 1];
    float a0 = g_P2[b * N + p0], a1 = g_P2[b * N + p1];
    float c0 = g_N2[b * N + p0], c1 = g_N2[b * N + p1];
    sp[t] = a0 + a1; sn[t] = c0 + c1;
    __syncthreads();
#pragma unroll
    for (int off = 1; off < 1024; off <<= 1) {
        float vp = (t >= off) ? sp[t - off] : 0.f;
        float vn = (t >= off) ? sn[t - off] : 0.f;
        __syncthreads();
        sp[t] += vp; sn[t] += vn;
        __syncthreads();
    }
    float basep = sp[t] - (a0 + a1);
    float basen = sn[t] - (c0 + c1);
    size_t o = (size_t)b * (N + 1);
    g_sP[o + 2 * t] = basep;        g_sN[o + 2 * t] = basen;
    g_sP[o + 2 * t + 1] = basep + a0; g_sN[o + 2 * t + 1] = basen + c0;
    if (t == 1023) { g_sP[o + N] = sp[1023]; g_sN[o + N] = sn[1023]; }
}

// ---------------------------------------------------------------------------
// Kernel 4: vector prefix scan of P2*h and N2*h in sorted order
//           (8 chunks of 256 per batch; chunk-local exclusive + chunk offsets)
// ---------------------------------------------------------------------------
__global__ __launch_bounds__(1024) void k_scan_vec() {
    __shared__ int   sperm[N];
    __shared__ float sp2[N], sn2[N];
    __shared__ float totP[NCHUNK][F], totN[NCHUNK][F];
    int b = blockIdx.x, t = threadIdx.x;

    for (int j = t; j < N; j += 1024) sperm[j] = g_perm[b * N + j];
    __syncthreads();
    for (int j = t; j < N; j += 1024) {
        int r = sperm[j];
        sp2[j] = g_P2[b * N + r];
        sn2[j] = g_N2[b * N + r];
    }
    __syncthreads();

    int g = t >> 7, f = t & 127;
    float accP = 0.f, accN = 0.f;
    int jbase = g * CHUNK;
#pragma unroll 4
    for (int jj = 0; jj < CHUNK; ++jj) {
        int j = jbase + jj;
        int row = sperm[j];
        float hv = g_h[((size_t)(b * N + row)) * F + f];
        size_t o = ((size_t)(b * N + j)) * F + f;
        g_SP[o] = accP;
        g_SN[o] = accN;
        accP = fmaf(sp2[j], hv, accP);
        accN = fmaf(sn2[j], hv, accN);
    }
    totP[g][f] = accP; totN[g][f] = accN;
    __syncthreads();

    if (t < F) {
        float op = 0.f, on = 0.f;
#pragma unroll
        for (int gg = 0; gg < NCHUNK; ++gg) {
            g_offP[((size_t)b * (NCHUNK + 1) + gg) * F + t] = op;
            g_offN[((size_t)b * (NCHUNK + 1) + gg) * F + t] = on;
            op += totP[gg][t]; on += totN[gg][t];
        }
        g_offP[((size_t)b * (NCHUNK + 1) + NCHUNK) * F + t] = op;
        g_offN[((size_t)b * (NCHUNK + 1) + NCHUNK) * F + t] = on;
    }
}

// ---------------------------------------------------------------------------
// Kernel 5: per-node lookup + epilogue
// ---------------------------------------------------------------------------
__global__ __launch_bounds__(128) void k_out(float* __restrict__ out) {
    __shared__ float negs[N];
    __shared__ int   kk[32];
    __shared__ float p1s[32], n1s[32];

    int t = threadIdx.x;
    int b = blockIdx.y;
    int i0 = blockIdx.x * 32;

    for (int j = t; j < N; j += 128) negs[j] = g_negs[b * N + j];
    __syncthreads();

    if (t < 32) {
        int i = b * N + i0 + t;
        float e1 = g_e1[i];
        int lo = 0, hi = N;
        while (lo < hi) {                 // first idx with negs[idx] >= e1
            int m = (lo + hi) >> 1;
            if (negs[m] < e1) lo = m + 1; else hi = m;
        }
        kk[t] = lo;
        p1s[t] = g_P1[i];
        n1s[t] = g_N1[i];
    }
    __syncthreads();

    float totNs = g_sN[(size_t)b * (N + 1) + N];
    float totNf = g_offN[((size_t)b * (NCHUNK + 1) + NCHUNK) * F + t];

#pragma unroll 2
    for (int r = 0; r < 32; ++r) {
        int k = kk[r];
        float P1 = p1s[r], N1v = n1s[r];
        float sPk = g_sP[(size_t)b * (N + 1) + k];
        float sNk = g_sN[(size_t)b * (N + 1) + k];
        float den = P1 * sPk + N1v * (totNs - sNk);

        float SPf, SNf;
        if (k == N) {
            SPf = g_offP[((size_t)b * (NCHUNK + 1) + NCHUNK) * F + t];
            SNf = totNf;
        } else {
            int g = k >> 8;
            SPf = g_offP[((size_t)b * (NCHUNK + 1) + g) * F + t]
                + g_SP[((size_t)(b * N + k)) * F + t];
            SNf = g_offN[((size_t)b * (NCHUNK + 1) + g) * F + t]
                + g_SN[((size_t)(b * N + k)) * F + t];
        }
        float num = P1 * SPf + N1v * (totNf - SNf);
        float hv = g_h[((size_t)(b * N + i0 + r)) * F + t];
        float x = num / den + GALPHA * hv;
        out[((size_t)(b * N + i0 + r)) * F + t] = (x > 0.f) ? x : expm1f(x);
    }
}

extern "C" void kernel_launch(void* const* d_in, const int* in_sizes, int n_in,
                              void* d_out, int out_size) {
    const float* text = (const float*)d_in[0];
    // d_in[1] = adj : unused by the reference computation
    const float* W = (const float*)d_in[2];
    const float* a = (const float*)d_in[3];
    float* out = (float*)d_out;

    k_gemm_h<<<(B * N) / 64, 256>>>(text, W, a);
    k_sort<<<B, 1024>>>();
    k_scan_scalar<<<B, 1024>>>();
    k_scan_vec<<<B, 1024>>>();
    dim3 g5(N / 32, B);
    k_out<<<g5, 128>>>(out);
}